// round 1
// baseline (speedup 1.0000x reference)
#include <cuda_runtime.h>
#include <math.h>

#define NN 100000
#define NE 3200000

// ---------------- scratch (device globals: allocation-free) ----------------
__device__ __align__(16) float g_x0[NN * 64];
__device__ __align__(16) float g_x1[NN * 64];
__device__ __align__(16) float g_x2[NN * 64];
__device__ __align__(16) float g_zl[NN * 64];
__device__ __align__(16) float g_zr[NN * 64];
__device__ __align__(16) float g_cat[NN * 96];
__device__ __align__(16) float g_xc[NN * 32];
__device__ float g_g[NN];
__device__ int g_deg[NN];
__device__ int g_cur[NN];
__device__ int g_off[NN];
__device__ int g_csr[NE];
__device__ float g_gm[16];
__device__ float g_gs[16];
__device__ float g_pool[512];

// ---------------- packed f32x2 helpers ----------------
__device__ __forceinline__ unsigned long long pack2(float x) {
    unsigned long long r;
    asm("mov.b64 %0, {%1, %1};" : "=l"(r) : "f"(x));
    return r;
}
__device__ __forceinline__ float2 unpack2(unsigned long long v) {
    float2 f;
    asm("mov.b64 {%0, %1}, %2;" : "=f"(f.x), "=f"(f.y) : "l"(v));
    return f;
}
#define FMA2(d, a, b) asm("fma.rn.f32x2 %0, %1, %2, %0;" : "+l"(d) : "l"(a), "l"(b))

__device__ __forceinline__ void atomicMaxF(float* addr, float val) {
    int* ia = (int*)addr;
    int old = *ia;
    while (__int_as_float(old) < val) {
        int assumed = old;
        old = atomicCAS(ia, assumed, __float_as_int(val));
        if (old == assumed) break;
    }
}

// ---------------- init / CSR build ----------------
__global__ void k_init(int n) {
    int i = blockIdx.x * blockDim.x + threadIdx.x;
    if (i < n) { g_deg[i] = 0; g_cur[i] = 0; }
    if (i < 16) { g_gm[i] = -INFINITY; g_gs[i] = 0.f; }
    if (i < 512) g_pool[i] = 0.f;
}

__global__ void k_hist(const int* __restrict__ dst, int e) {
    for (int i = blockIdx.x * blockDim.x + threadIdx.x; i < e; i += gridDim.x * blockDim.x)
        atomicAdd(&g_deg[dst[i]], 1);
}

__global__ void k_scan(int n) {
    __shared__ int ws[32];
    __shared__ int carry;
    int tid = threadIdx.x;
    if (tid == 0) carry = 0;
    __syncthreads();
    for (int base = 0; base < n; base += 1024) {
        int i = base + tid;
        int v = (i < n) ? g_deg[i] : 0;
        int incl = v;
        #pragma unroll
        for (int o = 1; o < 32; o <<= 1) {
            int t = __shfl_up_sync(0xffffffffu, incl, o);
            if ((tid & 31) >= o) incl += t;
        }
        if ((tid & 31) == 31) ws[tid >> 5] = incl;
        __syncthreads();
        if (tid < 32) {
            int wv = ws[tid];
            int wi = wv;
            #pragma unroll
            for (int o = 1; o < 32; o <<= 1) {
                int t = __shfl_up_sync(0xffffffffu, wi, o);
                if (tid >= o) wi += t;
            }
            ws[tid] = wi;
        }
        __syncthreads();
        int woff = (tid >= 32) ? ws[(tid >> 5) - 1] : 0;
        int excl = carry + woff + incl - v;
        if (i < n) g_off[i] = excl;
        int total = ws[31];
        __syncthreads();
        if (tid == 0) carry += total;
        __syncthreads();
    }
}

__global__ void k_fill(const int* __restrict__ src, const int* __restrict__ dst, int e) {
    for (int i = blockIdx.x * blockDim.x + threadIdx.x; i < e; i += gridDim.x * blockDim.x) {
        int d = dst[i];
        int pos = g_off[d] + atomicAdd(&g_cur[d], 1);
        g_csr[pos] = src[i];
    }
}

// ---------------- generic small-K row GEMM: out = in @ W (+b) (relu?) ----------------
// Tiled: ROWS rows staged in smem, thread = (row, colgroup of 16 cols spread in 4-col
// chunks for bank-conflict-free W loads). Packed f32x2 FMA.
template <int CI, int CO, int ROWS, bool BIAS, bool RELU>
__global__ void __launch_bounds__(ROWS*(CO / 16)) k_gemm(
    const float* __restrict__ in, const float* __restrict__ W, const float* __restrict__ bias,
    float* __restrict__ out, int outStride, int outOfs, int n)
{
    constexpr int NCG = CO / 16;
    constexpr int T = ROWS * NCG;
    constexpr int CIP = CI + 2;
    __shared__ float Xs[ROWS * CIP];
    __shared__ __align__(16) float Ws[CI * CO];
    __shared__ float bs[CO];
    int tid = threadIdx.x;
    for (int i = tid; i < CI * CO; i += T) Ws[i] = W[i];
    if (BIAS) for (int i = tid; i < CO; i += T) bs[i] = bias[i];
    int row0 = blockIdx.x * ROWS;
    for (int t = tid; t < ROWS * (CI / 4); t += T) {
        int r = t / (CI / 4), c = t % (CI / 4);
        int grr = row0 + r;
        float4 v = (grr < n) ? *(const float4*)&in[(size_t)grr * CI + c * 4]
                             : make_float4(0.f, 0.f, 0.f, 0.f);
        float* xp = &Xs[r * CIP + c * 4];
        xp[0] = v.x; xp[1] = v.y; xp[2] = v.z; xp[3] = v.w;
    }
    __syncthreads();
    int r = tid / NCG, cg = tid % NCG;
    const float* xrow = &Xs[r * CIP];
    unsigned long long acc[8];
    #pragma unroll
    for (int i = 0; i < 8; i++) acc[i] = 0ull;
    #pragma unroll 4
    for (int ci = 0; ci < CI; ci++) {
        unsigned long long xx = pack2(xrow[ci]);
        #pragma unroll
        for (int m = 0; m < 4; m++) {
            ulonglong2 w = *(const ulonglong2*)&Ws[ci * CO + cg * 4 + m * (NCG * 4)];
            FMA2(acc[2 * m], xx, w.x);
            FMA2(acc[2 * m + 1], xx, w.y);
        }
    }
    int gr = row0 + r;
    if (gr < n) {
        #pragma unroll
        for (int m = 0; m < 4; m++) {
            int cb = cg * 4 + m * (NCG * 4);
            float2 lo = unpack2(acc[2 * m]);
            float2 hi = unpack2(acc[2 * m + 1]);
            float4 o = make_float4(lo.x, lo.y, hi.x, hi.y);
            if (BIAS) { o.x += bs[cb]; o.y += bs[cb + 1]; o.z += bs[cb + 2]; o.w += bs[cb + 3]; }
            if (RELU) {
                o.x = fmaxf(o.x, 0.f); o.y = fmaxf(o.y, 0.f);
                o.z = fmaxf(o.z, 0.f); o.w = fmaxf(o.w, 0.f);
            }
            *(float4*)&out[(size_t)gr * outStride + outOfs + cb] = o;
        }
    }
}

// ---------------- CSR mean-aggregate + residual:  out = agg(zl)/max(deg,1) + lb + zr ----
__global__ void __launch_bounds__(256) k_aggr(
    const float* __restrict__ zl, const float* __restrict__ zr,
    const float* __restrict__ lb, float* __restrict__ out, int n)
{
    int warp = (blockIdx.x * blockDim.x + threadIdx.x) >> 5;
    int lane = threadIdx.x & 31;
    if (warp >= n) return;
    int s = g_off[warp], dgr = g_deg[warp];
    const float2* base = (const float2*)zl;
    float ax = 0.f, ay = 0.f;
    int k = 0;
    for (; k + 4 <= dgr; k += 4) {
        int i0 = g_csr[s + k], i1 = g_csr[s + k + 1], i2 = g_csr[s + k + 2], i3 = g_csr[s + k + 3];
        float2 a = __ldg(base + (size_t)i0 * 32 + lane);
        float2 b = __ldg(base + (size_t)i1 * 32 + lane);
        float2 c = __ldg(base + (size_t)i2 * 32 + lane);
        float2 d = __ldg(base + (size_t)i3 * 32 + lane);
        ax += (a.x + b.x) + (c.x + d.x);
        ay += (a.y + b.y) + (c.y + d.y);
    }
    for (; k < dgr; k++) {
        int i0 = g_csr[s + k];
        float2 a = __ldg(base + (size_t)i0 * 32 + lane);
        ax += a.x; ay += a.y;
    }
    float sc = 1.f / (float)(dgr > 0 ? dgr : 1);
    float2 r2 = ((const float2*)zr)[(size_t)warp * 32 + lane];
    float2 b2 = ((const float2*)lb)[lane];
    float2 o;
    o.x = ax * sc + b2.x + r2.x;
    o.y = ay * sc + b2.y + r2.y;
    ((float2*)out)[(size_t)warp * 32 + lane] = o;
}

// ---------------- gate: g = xc @ gate_w + gate_b ; per-graph max ----------------
__global__ void __launch_bounds__(256) k_gate(
    const float* __restrict__ gw, const float* __restrict__ gb,
    const int* __restrict__ batch, int n)
{
    __shared__ float sgw[32];
    __shared__ float sg[256];
    __shared__ int sb[256];
    int tid = threadIdx.x;
    if (tid < 32) sgw[tid] = gw[tid];
    __syncthreads();
    int r = blockIdx.x * 256 + tid;
    float g = -INFINITY; int b = -1;
    if (r < n) {
        const float4* xp = (const float4*)&g_xc[(size_t)r * 32];
        float acc = gb[0];
        #pragma unroll
        for (int i = 0; i < 8; i++) {
            float4 v = xp[i];
            acc += v.x * sgw[i * 4] + v.y * sgw[i * 4 + 1] + v.z * sgw[i * 4 + 2] + v.w * sgw[i * 4 + 3];
        }
        g = acc; g_g[r] = acc; b = batch[r];
    }
    sg[tid] = g; sb[tid] = b;
    __syncthreads();
    if (tid < 16) {
        float m = -INFINITY;
        for (int i = 0; i < 256; i++)
            if (sb[i] == tid) m = fmaxf(m, sg[i]);
        if (m > -INFINITY) atomicMaxF(&g_gm[tid], m);
    }
}

// ---------------- pool: sumE, sum(e * (xc@v_w+v_b)) per graph ----------------
__global__ void __launch_bounds__(256) k_pool(
    const float* __restrict__ vw, const float* __restrict__ vb,
    const int* __restrict__ batch, int n)
{
    __shared__ __align__(16) float sW[32 * 32];
    __shared__ float svb[32];
    __shared__ float sE[16];
    __shared__ float sV[512];
    int tid = threadIdx.x;
    for (int i = tid; i < 1024; i += 256) sW[i] = vw[i];
    if (tid < 32) svb[tid] = vb[tid];
    if (tid < 16) sE[tid] = 0.f;
    for (int i = tid; i < 512; i += 256) sV[i] = 0.f;
    __syncthreads();
    int r = blockIdx.x * 256 + tid;
    if (r < n) {
        int b = batch[r];
        float ec = expf(g_g[r] - g_gm[b]);
        const float4* xp = (const float4*)&g_xc[(size_t)r * 32];
        float4 xv[8];
        #pragma unroll
        for (int i = 0; i < 8; i++) xv[i] = xp[i];
        unsigned long long acc[16];
        #pragma unroll
        for (int p = 0; p < 16; p++) acc[p] = 0ull;
        #pragma unroll
        for (int i = 0; i < 8; i++) {
            #pragma unroll
            for (int kk = 0; kk < 4; kk++) {
                float f = (kk == 0) ? xv[i].x : (kk == 1) ? xv[i].y : (kk == 2) ? xv[i].z : xv[i].w;
                unsigned long long xx = pack2(f);
                int ci = i * 4 + kk;
                #pragma unroll
                for (int m = 0; m < 8; m++) {
                    ulonglong2 w = *(const ulonglong2*)&sW[ci * 32 + m * 4];
                    FMA2(acc[2 * m], xx, w.x);
                    FMA2(acc[2 * m + 1], xx, w.y);
                }
            }
        }
        float* sVb = &sV[b * 32];
        #pragma unroll
        for (int p = 0; p < 16; p++) {
            float2 v2 = unpack2(acc[p]);
            atomicAdd(&sVb[2 * p],     ec * (v2.x + svb[2 * p]));
            atomicAdd(&sVb[2 * p + 1], ec * (v2.y + svb[2 * p + 1]));
        }
        atomicAdd(&sE[b], ec);
    }
    __syncthreads();
    for (int i = tid; i < 512; i += 256) {
        float v = sV[i];
        if (v != 0.f) atomicAdd(&g_pool[i], v);
    }
    if (tid < 16) {
        float v = sE[tid];
        if (v != 0.f) atomicAdd(&g_gs[tid], v);
    }
}

// ---------------- final: pooled -> logits -> softmax ----------------
__global__ void k_final(const float* __restrict__ ow, const float* __restrict__ ob,
                        float* __restrict__ out) {
    int g = threadIdx.x;
    if (g < 16) {
        float inv = 1.f / g_gs[g];
        float l0 = ob[0], l1 = ob[1];
        #pragma unroll
        for (int c = 0; c < 32; c++) {
            float p = g_pool[g * 32 + c] * inv;
            l0 += p * ow[c * 2];
            l1 += p * ow[c * 2 + 1];
        }
        float m = fmaxf(l0, l1);
        float e0 = expf(l0 - m), e1 = expf(l1 - m);
        float s = e0 + e1;
        out[g * 2] = e0 / s;
        out[g * 2 + 1] = e1 / s;
        out[32 + g * 2] = l0;
        out[32 + g * 2 + 1] = l1;
    }
}

// ---------------- launcher ----------------
extern "C" void kernel_launch(void* const* d_in, const int* in_sizes, int n_in,
                              void* d_out, int out_size) {
    const float* x       = (const float*)d_in[0];
    const int*   ei      = (const int*)d_in[1];
    const int*   batch   = (const int*)d_in[2];
    const float* lin0_w  = (const float*)d_in[3];
    const float* lin0_b  = (const float*)d_in[4];
    const float* s1_lw   = (const float*)d_in[5];
    const float* s1_lb   = (const float*)d_in[6];
    const float* s1_rw   = (const float*)d_in[7];
    const float* s2_lw   = (const float*)d_in[8];
    const float* s2_lb   = (const float*)d_in[9];
    const float* s2_rw   = (const float*)d_in[10];
    const float* emb0_w  = (const float*)d_in[11];
    const float* emb0_b  = (const float*)d_in[12];
    const float* emb1_w  = (const float*)d_in[13];
    const float* emb1_b  = (const float*)d_in[14];
    const float* emb2_w  = (const float*)d_in[15];
    const float* emb2_b  = (const float*)d_in[16];
    const float* merge_w = (const float*)d_in[17];
    const float* merge_b = (const float*)d_in[18];
    const float* gate_w  = (const float*)d_in[19];
    const float* gate_b  = (const float*)d_in[20];
    const float* v_w     = (const float*)d_in[21];
    const float* v_b     = (const float*)d_in[22];
    const float* out_w   = (const float*)d_in[23];
    const float* out_b   = (const float*)d_in[24];
    float* out = (float*)d_out;

    int n = in_sizes[0] / 64;   // 100000
    int e = in_sizes[1] / 2;    // 3200000

    float *px0, *px1, *px2, *pzl, *pzr, *pcat, *pxc;
    cudaGetSymbolAddress((void**)&px0, g_x0);
    cudaGetSymbolAddress((void**)&px1, g_x1);
    cudaGetSymbolAddress((void**)&px2, g_x2);
    cudaGetSymbolAddress((void**)&pzl, g_zl);
    cudaGetSymbolAddress((void**)&pzr, g_zr);
    cudaGetSymbolAddress((void**)&pcat, g_cat);
    cudaGetSymbolAddress((void**)&pxc, g_xc);

    const int* srcp = ei;
    const int* dstp = ei + e;

    // CSR build (shared by both SAGE layers)
    k_init<<<(n + 255) / 256, 256>>>(n);
    k_hist<<<2048, 256>>>(dstp, e);
    k_scan<<<1, 1024>>>(n);
    k_fill<<<2048, 256>>>(srcp, dstp, e);

    int gb64 = (n + 63) / 64;    // ROWS=64
    int gb128 = (n + 127) / 128; // ROWS=128

    // x0 = x @ lin0_w + lin0_b
    k_gemm<64, 64, 64, true, false><<<gb64, 256>>>(x, lin0_w, lin0_b, px0, 64, 0, n);
    // SAGE 1
    k_gemm<64, 64, 64, false, false><<<gb64, 256>>>(px0, s1_lw, nullptr, pzl, 64, 0, n);
    k_gemm<64, 64, 64, false, false><<<gb64, 256>>>(px0, s1_rw, nullptr, pzr, 64, 0, n);
    k_aggr<<<(n * 32 + 255) / 256, 256>>>(pzl, pzr, s1_lb, px1, n);
    // SAGE 2
    k_gemm<64, 64, 64, false, false><<<gb64, 256>>>(px1, s2_lw, nullptr, pzl, 64, 0, n);
    k_gemm<64, 64, 64, false, false><<<gb64, 256>>>(px1, s2_rw, nullptr, pzr, 64, 0, n);
    k_aggr<<<(n * 32 + 255) / 256, 256>>>(pzl, pzr, s2_lb, px2, n);
    // embedding heads -> concat buffer (row stride 96)
    k_gemm<64, 32, 128, true, true><<<gb128, 256>>>(px0, emb0_w, emb0_b, pcat, 96, 0, n);
    k_gemm<64, 32, 128, true, true><<<gb128, 256>>>(px1, emb1_w, emb1_b, pcat, 96, 32, n);
    k_gemm<64, 32, 128, true, true><<<gb128, 256>>>(px2, emb2_w, emb2_b, pcat, 96, 64, n);
    // merge: xc = relu(cat @ merge_w + merge_b)
    k_gemm<96, 32, 64, true, true><<<gb64, 128>>>(pcat, merge_w, merge_b, pxc, 32, 0, n);
    // gate + per-graph max
    k_gate<<<(n + 255) / 256, 256>>>(gate_w, gate_b, batch, n);
    // attention pooling partial sums
    k_pool<<<(n + 255) / 256, 256>>>(v_w, v_b, batch, n);
    // logits + softmax
    k_final<<<1, 32>>>(out_w, out_b, out);
}

// round 7
// speedup vs baseline: 1.2426x; 1.2426x over previous
#include <cuda_runtime.h>
#include <math.h>

#define NN 100000
#define NE 3200000

// ---------------- scratch (device globals: allocation-free) ----------------
__device__ __align__(16) float g_x0[NN * 64];
__device__ __align__(16) float g_x1[NN * 64];
__device__ __align__(16) float g_x2[NN * 64];
__device__ __align__(16) float g_zl[NN * 64];
__device__ __align__(16) float g_zr[NN * 64];
__device__ __align__(16) float g_cat[NN * 96];
__device__ __align__(16) float g_xc[NN * 32];
__device__ float g_g[NN];
__device__ int g_deg[NN];
__device__ int g_off[NN];
__device__ int g_blk[128];
__device__ int g_csr[NE];
__device__ float g_gm[16];
__device__ float g_gs[16];
__device__ float g_pool[512];

// ---------------- packed f32x2 helpers ----------------
__device__ __forceinline__ unsigned long long pack2(float x) {
    unsigned long long r;
    asm("mov.b64 %0, {%1, %1};" : "=l"(r) : "f"(x));
    return r;
}
__device__ __forceinline__ float2 unpack2(unsigned long long v) {
    float2 f;
    asm("mov.b64 {%0, %1}, %2;" : "=f"(f.x), "=f"(f.y) : "l"(v));
    return f;
}
#define FMA2(d, a, b) asm("fma.rn.f32x2 %0, %1, %2, %0;" : "+l"(d) : "l"(a), "l"(b))

__device__ __forceinline__ void atomicMaxF(float* addr, float val) {
    int* ia = (int*)addr;
    int old = *ia;
    while (__int_as_float(old) < val) {
        int assumed = old;
        old = atomicCAS(ia, assumed, __float_as_int(val));
        if (old == assumed) break;
    }
}

// ---------------- init ----------------
__global__ void k_init(int n) {
    int i = blockIdx.x * blockDim.x + threadIdx.x;
    if (i < n) g_deg[i] = 0;
    if (i < 16) { g_gm[i] = -INFINITY; g_gs[i] = 0.f; }
    if (i < 512) g_pool[i] = 0.f;
}

// ---------------- histogram (int4 edge loads) ----------------
__global__ void k_hist(const int4* __restrict__ dst4, int e4) {
    for (int i = blockIdx.x * blockDim.x + threadIdx.x; i < e4; i += gridDim.x * blockDim.x) {
        int4 d = dst4[i];
        atomicAdd(&g_deg[d.x], 1);
        atomicAdd(&g_deg[d.y], 1);
        atomicAdd(&g_deg[d.z], 1);
        atomicAdd(&g_deg[d.w], 1);
    }
}

// ---------------- multi-block exclusive scan of degrees ----------------
// scan1: per-block (1024) exclusive scan into g_off, block totals to g_blk
__global__ void __launch_bounds__(1024) k_scan1(int n) {
    __shared__ int ws[32];
    int tid = threadIdx.x;
    int i = blockIdx.x * 1024 + tid;
    int v = (i < n) ? g_deg[i] : 0;
    int incl = v;
    #pragma unroll
    for (int o = 1; o < 32; o <<= 1) {
        int t = __shfl_up_sync(0xffffffffu, incl, o);
        if ((tid & 31) >= o) incl += t;
    }
    if ((tid & 31) == 31) ws[tid >> 5] = incl;
    __syncthreads();
    if (tid < 32) {
        int wi = ws[tid];
        #pragma unroll
        for (int o = 1; o < 32; o <<= 1) {
            int t = __shfl_up_sync(0xffffffffu, wi, o);
            if (tid >= o) wi += t;
        }
        ws[tid] = wi;
    }
    __syncthreads();
    int woff = (tid >= 32) ? ws[(tid >> 5) - 1] : 0;
    if (i < n) g_off[i] = woff + incl - v;
    if (tid == 1023) g_blk[blockIdx.x] = woff + incl;
}

// scan2: exclusive scan of block totals (nb <= 128), in place
__global__ void __launch_bounds__(128) k_scan2(int nb) {
    __shared__ int ws[4];
    int tid = threadIdx.x;
    int v = (tid < nb) ? g_blk[tid] : 0;
    int incl = v;
    #pragma unroll
    for (int o = 1; o < 32; o <<= 1) {
        int t = __shfl_up_sync(0xffffffffu, incl, o);
        if ((tid & 31) >= o) incl += t;
    }
    if ((tid & 31) == 31) ws[tid >> 5] = incl;
    __syncthreads();
    int add = 0;
    for (int j = 0; j < (tid >> 5); j++) add += ws[j];
    if (tid < nb) g_blk[tid] = add + incl - v;
}

// fill: pos = blk_base + atomic cursor on g_off (merged); int4 loads
__global__ void k_fill(const int4* __restrict__ src4, const int4* __restrict__ dst4, int e4) {
    for (int i = blockIdx.x * blockDim.x + threadIdx.x; i < e4; i += gridDim.x * blockDim.x) {
        int4 d = dst4[i];
        int4 s = src4[i];
        int p;
        p = g_blk[d.x >> 10] + atomicAdd(&g_off[d.x], 1); g_csr[p] = s.x;
        p = g_blk[d.y >> 10] + atomicAdd(&g_off[d.y], 1); g_csr[p] = s.y;
        p = g_blk[d.z >> 10] + atomicAdd(&g_off[d.z], 1); g_csr[p] = s.z;
        p = g_blk[d.w >> 10] + atomicAdd(&g_off[d.w], 1); g_csr[p] = s.w;
    }
}

// ---------------- register-blocked small-K GEMM ----------------
// thread = (row-group of R rows, col-group of 16 cols in 4 chunks of 4).
// W amortized over R rows. Packed f32x2 FMA.
// Static smem must stay under 48KB: Xs=ROWS*(CI+1)*4 + Ws=CI*CO*4 + CO*4.
template <int CI, int CO, int ROWS, int R, bool BIAS, bool RELU>
__global__ void __launch_bounds__((ROWS / R) * (CO / 16)) k_gemm(
    const float* __restrict__ in, const float* __restrict__ W, const float* __restrict__ bias,
    float* __restrict__ out, int outStride, int outOfs, int n)
{
    constexpr int NCG = CO / 16;
    constexpr int NRG = ROWS / R;
    constexpr int T = NRG * NCG;
    constexpr int CIP = CI + 1;   // odd pad: conflict-free x loads across row-groups
    __shared__ float Xs[ROWS * CIP];
    __shared__ __align__(16) float Ws[CI * CO];
    __shared__ float bs[CO];
    static_assert(sizeof(float) * (ROWS * CIP + CI * CO + CO) <= 48 * 1024, "smem");
    int tid = threadIdx.x;
    for (int i = tid; i < CI * CO; i += T) Ws[i] = W[i];
    if (BIAS) for (int i = tid; i < CO; i += T) bs[i] = bias[i];
    int row0 = blockIdx.x * ROWS;
    for (int t = tid; t < ROWS * (CI / 4); t += T) {
        int r = t / (CI / 4), c = t % (CI / 4);
        int grr = row0 + r;
        float4 v = (grr < n) ? *(const float4*)&in[(size_t)grr * CI + c * 4]
                             : make_float4(0.f, 0.f, 0.f, 0.f);
        float* xp = &Xs[r * CIP + c * 4];
        xp[0] = v.x; xp[1] = v.y; xp[2] = v.z; xp[3] = v.w;
    }
    __syncthreads();
    int rg = tid / NCG, cg = tid % NCG;
    const float* xb = &Xs[rg * R * CIP];
    unsigned long long acc[R * 8];
    #pragma unroll
    for (int i = 0; i < R * 8; i++) acc[i] = 0ull;
    #pragma unroll 4
    for (int ci = 0; ci < CI; ci++) {
        unsigned long long xx[R];
        #pragma unroll
        for (int r = 0; r < R; r++) xx[r] = pack2(xb[r * CIP + ci]);
        #pragma unroll
        for (int m = 0; m < 4; m++) {
            ulonglong2 w = *(const ulonglong2*)&Ws[ci * CO + cg * 4 + m * (NCG * 4)];
            #pragma unroll
            for (int r = 0; r < R; r++) {
                FMA2(acc[r * 8 + 2 * m], xx[r], w.x);
                FMA2(acc[r * 8 + 2 * m + 1], xx[r], w.y);
            }
        }
    }
    #pragma unroll
    for (int r = 0; r < R; r++) {
        int gr = row0 + rg * R + r;
        if (gr < n) {
            #pragma unroll
            for (int m = 0; m < 4; m++) {
                int cb = cg * 4 + m * (NCG * 4);
                float2 lo = unpack2(acc[r * 8 + 2 * m]);
                float2 hi = unpack2(acc[r * 8 + 2 * m + 1]);
                float4 o = make_float4(lo.x, lo.y, hi.x, hi.y);
                if (BIAS) { o.x += bs[cb]; o.y += bs[cb + 1]; o.z += bs[cb + 2]; o.w += bs[cb + 3]; }
                if (RELU) {
                    o.x = fmaxf(o.x, 0.f); o.y = fmaxf(o.y, 0.f);
                    o.z = fmaxf(o.z, 0.f); o.w = fmaxf(o.w, 0.f);
                }
                *(float4*)&out[(size_t)gr * outStride + outOfs + cb] = o;
            }
        }
    }
}

// ---------------- CSR mean-aggregate + residual:  out = agg(zl)/max(deg,1) + lb + zr ----
// 8-wide edge unroll: MLP=8 outstanding float2 gathers per warp-iter to cover
// ~250cyc L2-hit latency; mean degree ~32 keeps the main loop populated.
__global__ void __launch_bounds__(256) k_aggr(
    const float* __restrict__ zl, const float* __restrict__ zr,
    const float* __restrict__ lb, float* __restrict__ out, int n)
{
    int warp = (blockIdx.x * blockDim.x + threadIdx.x) >> 5;
    int lane = threadIdx.x & 31;
    if (warp >= n) return;
    int dgr = g_deg[warp];
    int s = g_blk[warp >> 10] + g_off[warp] - dgr;  // off advanced to end by k_fill
    const float2* base = (const float2*)zl;
    float ax = 0.f, ay = 0.f;
    int k = 0;
    for (; k + 8 <= dgr; k += 8) {
        int idx[8];
        #pragma unroll
        for (int j = 0; j < 8; j++) idx[j] = g_csr[s + k + j];
        float2 v[8];
        #pragma unroll
        for (int j = 0; j < 8; j++) v[j] = __ldg(base + (size_t)idx[j] * 32 + lane);
        float sx = 0.f, sy = 0.f;
        #pragma unroll
        for (int j = 0; j < 8; j++) { sx += v[j].x; sy += v[j].y; }
        ax += sx; ay += sy;
    }
    for (; k < dgr; k++) {
        int i0 = g_csr[s + k];
        float2 a = __ldg(base + (size_t)i0 * 32 + lane);
        ax += a.x; ay += a.y;
    }
    float sc = 1.f / (float)(dgr > 0 ? dgr : 1);
    float2 r2 = ((const float2*)zr)[(size_t)warp * 32 + lane];
    float2 b2 = ((const float2*)lb)[lane];
    float2 o;
    o.x = ax * sc + b2.x + r2.x;
    o.y = ay * sc + b2.y + r2.y;
    ((float2*)out)[(size_t)warp * 32 + lane] = o;
}

// ---------------- gate: g = xc @ gate_w + gate_b ; per-graph max ----------------
__global__ void __launch_bounds__(256) k_gate(
    const float* __restrict__ gw, const float* __restrict__ gb,
    const int* __restrict__ batch, int n)
{
    __shared__ float sgw[32];
    __shared__ float sg[256];
    __shared__ int sb[256];
    int tid = threadIdx.x;
    if (tid < 32) sgw[tid] = gw[tid];
    __syncthreads();
    int r = blockIdx.x * 256 + tid;
    float g = -INFINITY; int b = -1;
    if (r < n) {
        const float4* xp = (const float4*)&g_xc[(size_t)r * 32];
        float acc = gb[0];
        #pragma unroll
        for (int i = 0; i < 8; i++) {
            float4 v = xp[i];
            acc += v.x * sgw[i * 4] + v.y * sgw[i * 4 + 1] + v.z * sgw[i * 4 + 2] + v.w * sgw[i * 4 + 3];
        }
        g = acc; g_g[r] = acc; b = batch[r];
    }
    sg[tid] = g; sb[tid] = b;
    __syncthreads();
    if (tid < 16) {
        float m = -INFINITY;
        for (int i = 0; i < 256; i++)
            if (sb[i] == tid) m = fmaxf(m, sg[i]);
        if (m > -INFINITY) atomicMaxF(&g_gm[tid], m);
    }
}

// ---------------- pool: sumE, sum(e * (xc@v_w+v_b)) per graph ----------------
__global__ void __launch_bounds__(256) k_pool(
    const float* __restrict__ vw, const float* __restrict__ vb,
    const int* __restrict__ batch, int n)
{
    __shared__ __align__(16) float sW[32 * 32];
    __shared__ float svb[32];
    __shared__ float sE[16];
    __shared__ float sV[512];
    int tid = threadIdx.x;
    for (int i = tid; i < 1024; i += 256) sW[i] = vw[i];
    if (tid < 32) svb[tid] = vb[tid];
    if (tid < 16) sE[tid] = 0.f;
    for (int i = tid; i < 512; i += 256) sV[i] = 0.f;
    __syncthreads();
    int r = blockIdx.x * 256 + tid;
    if (r < n) {
        int b = batch[r];
        float ec = expf(g_g[r] - g_gm[b]);
        const float4* xp = (const float4*)&g_xc[(size_t)r * 32];
        float4 xv[8];
        #pragma unroll
        for (int i = 0; i < 8; i++) xv[i] = xp[i];
        unsigned long long acc[16];
        #pragma unroll
        for (int p = 0; p < 16; p++) acc[p] = 0ull;
        #pragma unroll
        for (int i = 0; i < 8; i++) {
            #pragma unroll
            for (int kk = 0; kk < 4; kk++) {
                float f = (kk == 0) ? xv[i].x : (kk == 1) ? xv[i].y : (kk == 2) ? xv[i].z : xv[i].w;
                unsigned long long xx = pack2(f);
                int ci = i * 4 + kk;
                #pragma unroll
                for (int m = 0; m < 8; m++) {
                    ulonglong2 w = *(const ulonglong2*)&sW[ci * 32 + m * 4];
                    FMA2(acc[2 * m], xx, w.x);
                    FMA2(acc[2 * m + 1], xx, w.y);
                }
            }
        }
        float* sVb = &sV[b * 32];
        #pragma unroll
        for (int p = 0; p < 16; p++) {
            float2 v2 = unpack2(acc[p]);
            atomicAdd(&sVb[2 * p],     ec * (v2.x + svb[2 * p]));
            atomicAdd(&sVb[2 * p + 1], ec * (v2.y + svb[2 * p + 1]));
        }
        atomicAdd(&sE[b], ec);
    }
    __syncthreads();
    for (int i = tid; i < 512; i += 256) {
        float v = sV[i];
        if (v != 0.f) atomicAdd(&g_pool[i], v);
    }
    if (tid < 16) {
        float v = sE[tid];
        if (v != 0.f) atomicAdd(&g_gs[tid], v);
    }
}

// ---------------- final: pooled -> logits -> softmax ----------------
__global__ void k_final(const float* __restrict__ ow, const float* __restrict__ ob,
                        float* __restrict__ out) {
    int g = threadIdx.x;
    if (g < 16) {
        float inv = 1.f / g_gs[g];
        float l0 = ob[0], l1 = ob[1];
        #pragma unroll
        for (int c = 0; c < 32; c++) {
            float p = g_pool[g * 32 + c] * inv;
            l0 += p * ow[c * 2];
            l1 += p * ow[c * 2 + 1];
        }
        float m = fmaxf(l0, l1);
        float e0 = expf(l0 - m), e1 = expf(l1 - m);
        float s = e0 + e1;
        out[g * 2] = e0 / s;
        out[g * 2 + 1] = e1 / s;
        out[32 + g * 2] = l0;
        out[32 + g * 2 + 1] = l1;
    }
}

// ---------------- launcher ----------------
extern "C" void kernel_launch(void* const* d_in, const int* in_sizes, int n_in,
                              void* d_out, int out_size) {
    const float* x       = (const float*)d_in[0];
    const int*   ei      = (const int*)d_in[1];
    const int*   batch   = (const int*)d_in[2];
    const float* lin0_w  = (const float*)d_in[3];
    const float* lin0_b  = (const float*)d_in[4];
    const float* s1_lw   = (const float*)d_in[5];
    const float* s1_lb   = (const float*)d_in[6];
    const float* s1_rw   = (const float*)d_in[7];
    const float* s2_lw   = (const float*)d_in[8];
    const float* s2_lb   = (const float*)d_in[9];
    const float* s2_rw   = (const float*)d_in[10];
    const float* emb0_w  = (const float*)d_in[11];
    const float* emb0_b  = (const float*)d_in[12];
    const float* emb1_w  = (const float*)d_in[13];
    const float* emb1_b  = (const float*)d_in[14];
    const float* emb2_w  = (const float*)d_in[15];
    const float* emb2_b  = (const float*)d_in[16];
    const float* merge_w = (const float*)d_in[17];
    const float* merge_b = (const float*)d_in[18];
    const float* gate_w  = (const float*)d_in[19];
    const float* gate_b  = (const float*)d_in[20];
    const float* v_w     = (const float*)d_in[21];
    const float* v_b     = (const float*)d_in[22];
    const float* out_w   = (const float*)d_in[23];
    const float* out_b   = (const float*)d_in[24];
    float* out = (float*)d_out;

    int n = in_sizes[0] / 64;   // 100000
    int e = in_sizes[1] / 2;    // 3200000
    int e4 = e / 4;
    int nb = (n + 1023) / 1024; // 98

    float *px0, *px1, *px2, *pzl, *pzr, *pcat, *pxc;
    cudaGetSymbolAddress((void**)&px0, g_x0);
    cudaGetSymbolAddress((void**)&px1, g_x1);
    cudaGetSymbolAddress((void**)&px2, g_x2);
    cudaGetSymbolAddress((void**)&pzl, g_zl);
    cudaGetSymbolAddress((void**)&pzr, g_zr);
    cudaGetSymbolAddress((void**)&pcat, g_cat);
    cudaGetSymbolAddress((void**)&pxc, g_xc);

    const int4* src4 = (const int4*)ei;
    const int4* dst4 = (const int4*)(ei + e);

    // CSR build (shared by both SAGE layers)
    k_init<<<(n + 255) / 256, 256>>>(n);
    k_hist<<<1024, 256>>>(dst4, e4);
    k_scan1<<<nb, 1024>>>(n);
    k_scan2<<<1, 128>>>(nb);
    k_fill<<<1024, 256>>>(src4, dst4, e4);

    int gb96 = (n + 95) / 96;     // 64x64 GEMMs: ROWS=96, 96 threads
    int gb128 = (n + 127) / 128;  // 64x32 GEMMs: ROWS=128, 128 threads
    int gb64 = (n + 63) / 64;     // 96x32 GEMM:  ROWS=64, 64 threads

    // x0 = x @ lin0_w + lin0_b
    k_gemm<64, 64, 96, 4, true, false><<<gb96, 96>>>(x, lin0_w, lin0_b, px0, 64, 0, n);
    // SAGE 1
    k_gemm<64, 64, 96, 4, false, false><<<gb96, 96>>>(px0, s1_lw, nullptr, pzl, 64, 0, n);
    k_gemm<64, 64, 96, 4, false, false><<<gb96, 96>>>(px0, s1_rw, nullptr, pzr, 64, 0, n);
    k_aggr<<<(n * 32 + 255) / 256, 256>>>(pzl, pzr, s1_lb, px1, n);
    // SAGE 2
    k_gemm<64, 64, 96, 4, false, false><<<gb96, 96>>>(px1, s2_lw, nullptr, pzl, 64, 0, n);
    k_gemm<64, 64, 96, 4, false, false><<<gb96, 96>>>(px1, s2_rw, nullptr, pzr, 64, 0, n);
    k_aggr<<<(n * 32 + 255) / 256, 256>>>(pzl, pzr, s2_lb, px2, n);
    // embedding heads -> concat buffer (row stride 96)
    k_gemm<64, 32, 128, 2, true, true><<<gb128, 128>>>(px0, emb0_w, emb0_b, pcat, 96, 0, n);
    k_gemm<64, 32, 128, 2, true, true><<<gb128, 128>>>(px1, emb1_w, emb1_b, pcat, 96, 32, n);
    k_gemm<64, 32, 128, 2, true, true><<<gb128, 128>>>(px2, emb2_w, emb2_b, pcat, 96, 64, n);
    // merge: xc = relu(cat @ merge_w + merge_b)
    k_gemm<96, 32, 64, 2, true, true><<<gb64, 64>>>(pcat, merge_w, merge_b, pxc, 32, 0, n);
    // gate + per-graph max
    k_gate<<<(n + 255) / 256, 256>>>(gate_w, gate_b, batch, n);
    // attention pooling partial sums
    k_pool<<<(n + 255) / 256, 256>>>(v_w, v_b, batch, n);
    // logits + softmax
    k_final<<<1, 32>>>(out_w, out_b, out);
}

// round 11
// speedup vs baseline: 1.4001x; 1.1268x over previous
#include <cuda_runtime.h>
#include <math.h>

#define NN 100000
#define NE 3200000

// ---------------- scratch (device globals: allocation-free) ----------------
__device__ __align__(16) float g_x0[NN * 64];
__device__ __align__(16) float g_x1[NN * 64];
__device__ __align__(16) float g_x2[NN * 64];
__device__ __align__(16) float g_zl[NN * 64];
__device__ __align__(16) float g_zr[NN * 64];
__device__ __align__(16) float g_cat[NN * 96];
__device__ __align__(16) float g_xc[NN * 32];
__device__ float g_g[NN];
__device__ int g_deg[NN];
__device__ int g_off[NN];
__device__ int g_blk[128];
__device__ int g_csr[NE];
__device__ float g_gm[16];
__device__ float g_gs[16];
__device__ float g_pool[512];
__device__ unsigned int g_cnt;

// ---------------- packed f32x2 helpers ----------------
__device__ __forceinline__ unsigned long long pack2(float x) {
    unsigned long long r;
    asm("mov.b64 %0, {%1, %1};" : "=l"(r) : "f"(x));
    return r;
}
__device__ __forceinline__ float2 unpack2(unsigned long long v) {
    float2 f;
    asm("mov.b64 {%0, %1}, %2;" : "=f"(f.x), "=f"(f.y) : "l"(v));
    return f;
}
#define FMA2(d, a, b) asm("fma.rn.f32x2 %0, %1, %2, %0;" : "+l"(d) : "l"(a), "l"(b))

__device__ __forceinline__ void atomicMaxF(float* addr, float val) {
    int* ia = (int*)addr;
    int old = *ia;
    while (__int_as_float(old) < val) {
        int assumed = old;
        old = atomicCAS(ia, assumed, __float_as_int(val));
        if (old == assumed) break;
    }
}

// ---------------- init ----------------
__global__ void k_init(int n) {
    int i = blockIdx.x * blockDim.x + threadIdx.x;
    if (i < n) g_deg[i] = 0;
    if (i < 16) { g_gm[i] = -INFINITY; g_gs[i] = 0.f; }
    if (i < 512) g_pool[i] = 0.f;
    if (i == 600) g_cnt = 0;
}

// ---------------- histogram (int4 edge loads) ----------------
__global__ void k_hist(const int4* __restrict__ dst4, int e4) {
    for (int i = blockIdx.x * blockDim.x + threadIdx.x; i < e4; i += gridDim.x * blockDim.x) {
        int4 d = dst4[i];
        atomicAdd(&g_deg[d.x], 1);
        atomicAdd(&g_deg[d.y], 1);
        atomicAdd(&g_deg[d.z], 1);
        atomicAdd(&g_deg[d.w], 1);
    }
}

// scan1: per-block (1024) exclusive scan into g_off, block TOTALS to g_blk
__global__ void __launch_bounds__(1024) k_scan1(int n) {
    __shared__ int ws[32];
    int tid = threadIdx.x;
    int i = blockIdx.x * 1024 + tid;
    int v = (i < n) ? g_deg[i] : 0;
    int incl = v;
    #pragma unroll
    for (int o = 1; o < 32; o <<= 1) {
        int t = __shfl_up_sync(0xffffffffu, incl, o);
        if ((tid & 31) >= o) incl += t;
    }
    if ((tid & 31) == 31) ws[tid >> 5] = incl;
    __syncthreads();
    if (tid < 32) {
        int wi = ws[tid];
        #pragma unroll
        for (int o = 1; o < 32; o <<= 1) {
            int t = __shfl_up_sync(0xffffffffu, wi, o);
            if (tid >= o) wi += t;
        }
        ws[tid] = wi;
    }
    __syncthreads();
    int woff = (tid >= 32) ? ws[(tid >> 5) - 1] : 0;
    if (i < n) g_off[i] = woff + incl - v;
    if (tid == 1023) g_blk[blockIdx.x] = woff + incl;
}

// local exclusive scan of g_blk totals into sblk (block-resident; nb<=128).
__device__ __forceinline__ void local_blk_scan(int* sblk, int* sws, int nb) {
    int tid = threadIdx.x;
    int v = 0, incl = 0;
    if (tid < 128) {
        v = (tid < nb) ? g_blk[tid] : 0;
        incl = v;
        #pragma unroll
        for (int o = 1; o < 32; o <<= 1) {
            int t = __shfl_up_sync(0xffffffffu, incl, o);
            if ((tid & 31) >= o) incl += t;
        }
        if ((tid & 31) == 31) sws[tid >> 5] = incl;
    }
    __syncthreads();
    if (tid < 128) {
        int add = 0;
        for (int j = 0; j < (tid >> 5); j++) add += sws[j];
        sblk[tid] = add + incl - v;
    }
    __syncthreads();
}

// fill: pos = local blk prefix + atomic cursor on g_off (merged); int4 loads
__global__ void __launch_bounds__(256) k_fill(const int4* __restrict__ src4,
                                              const int4* __restrict__ dst4, int e4, int nb) {
    __shared__ int sblk[128];
    __shared__ int sws[4];
    local_blk_scan(sblk, sws, nb);
    for (int i = blockIdx.x * blockDim.x + threadIdx.x; i < e4; i += gridDim.x * blockDim.x) {
        int4 d = dst4[i];
        int4 s = src4[i];
        int p;
        p = sblk[d.x >> 10] + atomicAdd(&g_off[d.x], 1); g_csr[p] = s.x;
        p = sblk[d.y >> 10] + atomicAdd(&g_off[d.y], 1); g_csr[p] = s.y;
        p = sblk[d.z >> 10] + atomicAdd(&g_off[d.z], 1); g_csr[p] = s.z;
        p = sblk[d.w >> 10] + atomicAdd(&g_off[d.w], 1); g_csr[p] = s.w;
    }
}

// ---------------- register-blocked small-K GEMM (single W) ----------------
template <int CI, int CO, int ROWS, int R, bool BIAS, bool RELU>
__global__ void __launch_bounds__((ROWS / R) * (CO / 16)) k_gemm(
    const float* __restrict__ in, const float* __restrict__ W, const float* __restrict__ bias,
    float* __restrict__ out, int outStride, int outOfs, int n)
{
    constexpr int NCG = CO / 16;
    constexpr int NRG = ROWS / R;
    constexpr int T = NRG * NCG;
    constexpr int CIP = CI + 1;
    __shared__ float Xs[ROWS * CIP];
    __shared__ __align__(16) float Ws[CI * CO];
    __shared__ float bs[CO];
    static_assert(sizeof(float) * (ROWS * CIP + CI * CO + CO) <= 48 * 1024, "smem");
    int tid = threadIdx.x;
    for (int i = tid; i < CI * CO; i += T) Ws[i] = W[i];
    if (BIAS) for (int i = tid; i < CO; i += T) bs[i] = bias[i];
    int row0 = blockIdx.x * ROWS;
    for (int t = tid; t < ROWS * (CI / 4); t += T) {
        int r = t / (CI / 4), c = t % (CI / 4);
        int grr = row0 + r;
        float4 v = (grr < n) ? *(const float4*)&in[(size_t)grr * CI + c * 4]
                             : make_float4(0.f, 0.f, 0.f, 0.f);
        float* xp = &Xs[r * CIP + c * 4];
        xp[0] = v.x; xp[1] = v.y; xp[2] = v.z; xp[3] = v.w;
    }
    __syncthreads();
    int rg = tid / NCG, cg = tid % NCG;
    const float* xb = &Xs[rg * R * CIP];
    unsigned long long acc[R * 8];
    #pragma unroll
    for (int i = 0; i < R * 8; i++) acc[i] = 0ull;
    #pragma unroll 4
    for (int ci = 0; ci < CI; ci++) {
        unsigned long long xx[R];
        #pragma unroll
        for (int r = 0; r < R; r++) xx[r] = pack2(xb[r * CIP + ci]);
        #pragma unroll
        for (int m = 0; m < 4; m++) {
            ulonglong2 w = *(const ulonglong2*)&Ws[ci * CO + cg * 4 + m * (NCG * 4)];
            #pragma unroll
            for (int r = 0; r < R; r++) {
                FMA2(acc[r * 8 + 2 * m], xx[r], w.x);
                FMA2(acc[r * 8 + 2 * m + 1], xx[r], w.y);
            }
        }
    }
    #pragma unroll
    for (int r = 0; r < R; r++) {
        int gr = row0 + rg * R + r;
        if (gr < n) {
            #pragma unroll
            for (int m = 0; m < 4; m++) {
                int cb = cg * 4 + m * (NCG * 4);
                float2 lo = unpack2(acc[r * 8 + 2 * m]);
                float2 hi = unpack2(acc[r * 8 + 2 * m + 1]);
                float4 o = make_float4(lo.x, lo.y, hi.x, hi.y);
                if (BIAS) { o.x += bs[cb]; o.y += bs[cb + 1]; o.z += bs[cb + 2]; o.w += bs[cb + 3]; }
                if (RELU) {
                    o.x = fmaxf(o.x, 0.f); o.y = fmaxf(o.y, 0.f);
                    o.z = fmaxf(o.z, 0.f); o.w = fmaxf(o.w, 0.f);
                }
                *(float4*)&out[(size_t)gr * outStride + outOfs + cb] = o;
            }
        }
    }
}

// ---------------- dual-W GEMM: one Xs staging, two W phases ----------------
template <int CI, int CO, int ROWS, int R>
__global__ void __launch_bounds__((ROWS / R) * (CO / 16)) k_gemm2(
    const float* __restrict__ in, const float* __restrict__ Wl, const float* __restrict__ Wr,
    float* __restrict__ outl, float* __restrict__ outr, int n)
{
    constexpr int NCG = CO / 16;
    constexpr int NRG = ROWS / R;
    constexpr int T = NRG * NCG;
    constexpr int CIP = CI + 1;
    __shared__ float Xs[ROWS * CIP];
    __shared__ __align__(16) float Ws[CI * CO];
    static_assert(sizeof(float) * (ROWS * CIP + CI * CO) <= 48 * 1024, "smem");
    int tid = threadIdx.x;
    int row0 = blockIdx.x * ROWS;
    for (int t = tid; t < ROWS * (CI / 4); t += T) {
        int r = t / (CI / 4), c = t % (CI / 4);
        int grr = row0 + r;
        float4 v = (grr < n) ? *(const float4*)&in[(size_t)grr * CI + c * 4]
                             : make_float4(0.f, 0.f, 0.f, 0.f);
        float* xp = &Xs[r * CIP + c * 4];
        xp[0] = v.x; xp[1] = v.y; xp[2] = v.z; xp[3] = v.w;
    }
    int rg = tid / NCG, cg = tid % NCG;
    const float* xb = &Xs[rg * R * CIP];
    #pragma unroll
    for (int ph = 0; ph < 2; ph++) {
        const float* W = (ph == 0) ? Wl : Wr;
        float* out = (ph == 0) ? outl : outr;
        for (int i = tid; i < CI * CO; i += T) Ws[i] = W[i];
        __syncthreads();
        unsigned long long acc[R * 8];
        #pragma unroll
        for (int i = 0; i < R * 8; i++) acc[i] = 0ull;
        #pragma unroll 4
        for (int ci = 0; ci < CI; ci++) {
            unsigned long long xx[R];
            #pragma unroll
            for (int r = 0; r < R; r++) xx[r] = pack2(xb[r * CIP + ci]);
            #pragma unroll
            for (int m = 0; m < 4; m++) {
                ulonglong2 w = *(const ulonglong2*)&Ws[ci * CO + cg * 4 + m * (NCG * 4)];
                #pragma unroll
                for (int r = 0; r < R; r++) {
                    FMA2(acc[r * 8 + 2 * m], xx[r], w.x);
                    FMA2(acc[r * 8 + 2 * m + 1], xx[r], w.y);
                }
            }
        }
        #pragma unroll
        for (int r = 0; r < R; r++) {
            int gr = row0 + rg * R + r;
            if (gr < n) {
                #pragma unroll
                for (int m = 0; m < 4; m++) {
                    int cb = cg * 4 + m * (NCG * 4);
                    float2 lo = unpack2(acc[r * 8 + 2 * m]);
                    float2 hi = unpack2(acc[r * 8 + 2 * m + 1]);
                    float4 o = make_float4(lo.x, lo.y, hi.x, hi.y);
                    *(float4*)&out[(size_t)gr * CO + cb] = o;
                }
            }
        }
        __syncthreads();
    }
}

// ---------------- three 64->32 embedding GEMMs (relu) in one launch --------
__global__ void __launch_bounds__(128) k_emb3(
    const float* __restrict__ x0, const float* __restrict__ x1, const float* __restrict__ x2,
    const float* __restrict__ w0, const float* __restrict__ w1, const float* __restrict__ w2,
    const float* __restrict__ b0, const float* __restrict__ b1, const float* __restrict__ b2,
    float* __restrict__ cat, int n)
{
    constexpr int CI = 64, CO = 32, ROWS = 128, R = 2;
    constexpr int NCG = CO / 16;
    constexpr int T = (ROWS / R) * NCG;
    constexpr int CIP = CI + 1;
    __shared__ float Xs[ROWS * CIP];
    __shared__ __align__(16) float Ws[CI * CO];
    __shared__ float bs[CO];
    int tid = threadIdx.x;
    int row0 = blockIdx.x * ROWS;
    int rg = tid / NCG, cg = tid % NCG;
    const float* xb = &Xs[rg * R * CIP];
    const float* xin[3] = {x0, x1, x2};
    const float* win[3] = {w0, w1, w2};
    const float* bin[3] = {b0, b1, b2};
    for (int p = 0; p < 3; p++) {
        const float* in = xin[p];
        for (int i = tid; i < CI * CO; i += T) Ws[i] = win[p][i];
        if (tid < CO) bs[tid] = bin[p][tid];
        for (int t = tid; t < ROWS * (CI / 4); t += T) {
            int r = t / (CI / 4), c = t % (CI / 4);
            int grr = row0 + r;
            float4 v = (grr < n) ? *(const float4*)&in[(size_t)grr * CI + c * 4]
                                 : make_float4(0.f, 0.f, 0.f, 0.f);
            float* xp = &Xs[r * CIP + c * 4];
            xp[0] = v.x; xp[1] = v.y; xp[2] = v.z; xp[3] = v.w;
        }
        __syncthreads();
        unsigned long long acc[R * 8];
        #pragma unroll
        for (int i = 0; i < R * 8; i++) acc[i] = 0ull;
        #pragma unroll 4
        for (int ci = 0; ci < CI; ci++) {
            unsigned long long xx[R];
            #pragma unroll
            for (int r = 0; r < R; r++) xx[r] = pack2(xb[r * CIP + ci]);
            #pragma unroll
            for (int m = 0; m < 4; m++) {
                ulonglong2 w = *(const ulonglong2*)&Ws[ci * CO + cg * 4 + m * (NCG * 4)];
                #pragma unroll
                for (int r = 0; r < R; r++) {
                    FMA2(acc[r * 8 + 2 * m], xx[r], w.x);
                    FMA2(acc[r * 8 + 2 * m + 1], xx[r], w.y);
                }
            }
        }
        #pragma unroll
        for (int r = 0; r < R; r++) {
            int gr = row0 + rg * R + r;
            if (gr < n) {
                #pragma unroll
                for (int m = 0; m < 4; m++) {
                    int cb = cg * 4 + m * (NCG * 4);
                    float2 lo = unpack2(acc[r * 8 + 2 * m]);
                    float2 hi = unpack2(acc[r * 8 + 2 * m + 1]);
                    float4 o = make_float4(fmaxf(lo.x + bs[cb], 0.f), fmaxf(lo.y + bs[cb + 1], 0.f),
                                           fmaxf(hi.x + bs[cb + 2], 0.f), fmaxf(hi.y + bs[cb + 3], 0.f));
                    *(float4*)&cat[(size_t)gr * 96 + 32 * p + cb] = o;
                }
            }
        }
        __syncthreads();
    }
}

// ---------------- merge GEMM (96->32, relu) + fused gate ----------------
__global__ void __launch_bounds__(64) k_merge(
    const float* __restrict__ in, const float* __restrict__ W, const float* __restrict__ bias,
    const float* __restrict__ gw, const float* __restrict__ gb,
    const int* __restrict__ batch, float* __restrict__ out, int n)
{
    constexpr int CI = 96, CO = 32, ROWS = 64, R = 2;
    constexpr int NCG = CO / 16;
    constexpr int T = (ROWS / R) * NCG;
    constexpr int CIP = CI + 1;
    __shared__ float Xs[ROWS * CIP];
    __shared__ __align__(16) float Ws[CI * CO];
    __shared__ float bs[CO];
    __shared__ float sgw[CO];
    int tid = threadIdx.x;
    for (int i = tid; i < CI * CO; i += T) Ws[i] = W[i];
    if (tid < CO) { bs[tid] = bias[tid]; sgw[tid] = gw[tid]; }
    int row0 = blockIdx.x * ROWS;
    for (int t = tid; t < ROWS * (CI / 4); t += T) {
        int r = t / (CI / 4), c = t % (CI / 4);
        int grr = row0 + r;
        float4 v = (grr < n) ? *(const float4*)&in[(size_t)grr * CI + c * 4]
                             : make_float4(0.f, 0.f, 0.f, 0.f);
        float* xp = &Xs[r * CIP + c * 4];
        xp[0] = v.x; xp[1] = v.y; xp[2] = v.z; xp[3] = v.w;
    }
    __syncthreads();
    int rg = tid / NCG, cg = tid % NCG;
    const float* xb = &Xs[rg * R * CIP];
    unsigned long long acc[R * 8];
    #pragma unroll
    for (int i = 0; i < R * 8; i++) acc[i] = 0ull;
    #pragma unroll 4
    for (int ci = 0; ci < CI; ci++) {
        unsigned long long xx[R];
        #pragma unroll
        for (int r = 0; r < R; r++) xx[r] = pack2(xb[r * CIP + ci]);
        #pragma unroll
        for (int m = 0; m < 4; m++) {
            ulonglong2 w = *(const ulonglong2*)&Ws[ci * CO + cg * 4 + m * (NCG * 4)];
            #pragma unroll
            for (int r = 0; r < R; r++) {
                FMA2(acc[r * 8 + 2 * m], xx[r], w.x);
                FMA2(acc[r * 8 + 2 * m + 1], xx[r], w.y);
            }
        }
    }
    float gp[R] = {0.f, 0.f};
    #pragma unroll
    for (int r = 0; r < R; r++) {
        int gr = row0 + rg * R + r;
        if (gr < n) {
            #pragma unroll
            for (int m = 0; m < 4; m++) {
                int cb = cg * 4 + m * (NCG * 4);
                float2 lo = unpack2(acc[r * 8 + 2 * m]);
                float2 hi = unpack2(acc[r * 8 + 2 * m + 1]);
                float4 o = make_float4(fmaxf(lo.x + bs[cb], 0.f), fmaxf(lo.y + bs[cb + 1], 0.f),
                                       fmaxf(hi.x + bs[cb + 2], 0.f), fmaxf(hi.y + bs[cb + 3], 0.f));
                *(float4*)&out[(size_t)gr * CO + cb] = o;
                gp[r] += o.x * sgw[cb] + o.y * sgw[cb + 1] + o.z * sgw[cb + 2] + o.w * sgw[cb + 3];
            }
        }
    }
    #pragma unroll
    for (int r = 0; r < R; r++) {
        float tot = gp[r] + __shfl_xor_sync(0xffffffffu, gp[r], 1);
        int gr = row0 + rg * R + r;
        if (cg == 0 && gr < n) {
            float g = tot + gb[0];
            g_g[gr] = g;
            atomicMaxF(&g_gm[batch[gr]], g);
        }
    }
}

// ---------------- CSR mean-aggregate + residual (MLP=8, local blk scan) ----
__global__ void __launch_bounds__(256) k_aggr(
    const float* __restrict__ zl, const float* __restrict__ zr,
    const float* __restrict__ lb, float* __restrict__ out, int n, int nb)
{
    __shared__ int sblk[128];
    __shared__ int sws[4];
    local_blk_scan(sblk, sws, nb);
    int node = blockIdx.x * 8 + (threadIdx.x >> 5);
    int lane = threadIdx.x & 31;
    if (node >= n) return;
    int dgr = g_deg[node];
    int s = sblk[node >> 10] + g_off[node] - dgr;
    const float2* base = (const float2*)zl;
    float ax = 0.f, ay = 0.f;
    int k = 0;
    for (; k + 8 <= dgr; k += 8) {
        int idx[8];
        #pragma unroll
        for (int j = 0; j < 8; j++) idx[j] = g_csr[s + k + j];
        float2 v[8];
        #pragma unroll
        for (int j = 0; j < 8; j++) v[j] = __ldg(base + (size_t)idx[j] * 32 + lane);
        float sx = 0.f, sy = 0.f;
        #pragma unroll
        for (int j = 0; j < 8; j++) { sx += v[j].x; sy += v[j].y; }
        ax += sx; ay += sy;
    }
    for (; k < dgr; k++) {
        int i0 = g_csr[s + k];
        float2 a = __ldg(base + (size_t)i0 * 32 + lane);
        ax += a.x; ay += a.y;
    }
    float sc = 1.f / (float)(dgr > 0 ? dgr : 1);
    float2 r2 = ((const float2*)zr)[(size_t)node * 32 + lane];
    float2 b2 = ((const float2*)lb)[lane];
    float2 o;
    o.x = ax * sc + b2.x + r2.x;
    o.y = ay * sc + b2.y + r2.y;
    ((float2*)out)[(size_t)node * 32 + lane] = o;
}

// ---------------- pool + fused final (last-block pattern) ----------------
__global__ void __launch_bounds__(256) k_pool(
    const float* __restrict__ vw, const float* __restrict__ vb,
    const int* __restrict__ batch,
    const float* __restrict__ ow, const float* __restrict__ ob,
    float* __restrict__ outbuf, int n)
{
    __shared__ __align__(16) float sW[32 * 32];
    __shared__ float svb[32];
    __shared__ float sE[16];
    __shared__ float sV[512];
    __shared__ bool last;
    int tid = threadIdx.x;
    for (int i = tid; i < 1024; i += 256) sW[i] = vw[i];
    if (tid < 32) svb[tid] = vb[tid];
    if (tid < 16) sE[tid] = 0.f;
    for (int i = tid; i < 512; i += 256) sV[i] = 0.f;
    __syncthreads();
    int r = blockIdx.x * 256 + tid;
    if (r < n) {
        int b = batch[r];
        float ec = expf(g_g[r] - g_gm[b]);
        const float4* xp = (const float4*)&g_xc[(size_t)r * 32];
        float4 xv[8];
        #pragma unroll
        for (int i = 0; i < 8; i++) xv[i] = xp[i];
        unsigned long long acc[16];
        #pragma unroll
        for (int p = 0; p < 16; p++) acc[p] = 0ull;
        #pragma unroll
        for (int i = 0; i < 8; i++) {
            #pragma unroll
            for (int kk = 0; kk < 4; kk++) {
                float f = (kk == 0) ? xv[i].x : (kk == 1) ? xv[i].y : (kk == 2) ? xv[i].z : xv[i].w;
                unsigned long long xx = pack2(f);
                int ci = i * 4 + kk;
                #pragma unroll
                for (int m = 0; m < 8; m++) {
                    ulonglong2 w = *(const ulonglong2*)&sW[ci * 32 + m * 4];
                    FMA2(acc[2 * m], xx, w.x);
                    FMA2(acc[2 * m + 1], xx, w.y);
                }
            }
        }
        float* sVb = &sV[b * 32];
        #pragma unroll
        for (int p = 0; p < 16; p++) {
            float2 v2 = unpack2(acc[p]);
            atomicAdd(&sVb[2 * p],     ec * (v2.x + svb[2 * p]));
            atomicAdd(&sVb[2 * p + 1], ec * (v2.y + svb[2 * p + 1]));
        }
        atomicAdd(&sE[b], ec);
    }
    __syncthreads();
    for (int i = tid; i < 512; i += 256) {
        float v = sV[i];
        if (v != 0.f) atomicAdd(&g_pool[i], v);
    }
    if (tid < 16) {
        float v = sE[tid];
        if (v != 0.f) atomicAdd(&g_gs[tid], v);
    }
    __threadfence();
    if (tid == 0) last = (atomicAdd(&g_cnt, 1u) == gridDim.x - 1);
    __syncthreads();
    if (last && tid < 16) {
        int g = tid;
        float inv = 1.f / __ldcg(&g_gs[g]);
        float l0 = ob[0], l1 = ob[1];
        #pragma unroll
        for (int c = 0; c < 32; c++) {
            float p = __ldcg(&g_pool[g * 32 + c]) * inv;
            l0 += p * ow[c * 2];
            l1 += p * ow[c * 2 + 1];
        }
        float m = fmaxf(l0, l1);
        float e0 = expf(l0 - m), e1 = expf(l1 - m);
        float s = e0 + e1;
        outbuf[g * 2] = e0 / s;
        outbuf[g * 2 + 1] = e1 / s;
        outbuf[32 + g * 2] = l0;
        outbuf[32 + g * 2 + 1] = l1;
    }
}

// ---------------- launcher ----------------
extern "C" void kernel_launch(void* const* d_in, const int* in_sizes, int n_in,
                              void* d_out, int out_size) {
    const float* x       = (const float*)d_in[0];
    const int*   ei      = (const int*)d_in[1];
    const int*   batch   = (const int*)d_in[2];
    const float* lin0_w  = (const float*)d_in[3];
    const float* lin0_b  = (const float*)d_in[4];
    const float* s1_lw   = (const float*)d_in[5];
    const float* s1_lb   = (const float*)d_in[6];
    const float* s1_rw   = (const float*)d_in[7];
    const float* s2_lw   = (const float*)d_in[8];
    const float* s2_lb   = (const float*)d_in[9];
    const float* s2_rw   = (const float*)d_in[10];
    const float* emb0_w  = (const float*)d_in[11];
    const float* emb0_b  = (const float*)d_in[12];
    const float* emb1_w  = (const float*)d_in[13];
    const float* emb1_b  = (const float*)d_in[14];
    const float* emb2_w  = (const float*)d_in[15];
    const float* emb2_b  = (const float*)d_in[16];
    const float* merge_w = (const float*)d_in[17];
    const float* merge_b = (const float*)d_in[18];
    const float* gate_w  = (const float*)d_in[19];
    const float* gate_b  = (const float*)d_in[20];
    const float* v_w     = (const float*)d_in[21];
    const float* v_b     = (const float*)d_in[22];
    const float* out_w   = (const float*)d_in[23];
    const float* out_b   = (const float*)d_in[24];
    float* out = (float*)d_out;

    int n = in_sizes[0] / 64;   // 100000
    int e = in_sizes[1] / 2;    // 3200000
    int e4 = e / 4;
    int nb = (n + 1023) / 1024; // 98

    float *px0, *px1, *px2, *pzl, *pzr, *pcat, *pxc;
    cudaGetSymbolAddress((void**)&px0, g_x0);
    cudaGetSymbolAddress((void**)&px1, g_x1);
    cudaGetSymbolAddress((void**)&px2, g_x2);
    cudaGetSymbolAddress((void**)&pzl, g_zl);
    cudaGetSymbolAddress((void**)&pzr, g_zr);
    cudaGetSymbolAddress((void**)&pcat, g_cat);
    cudaGetSymbolAddress((void**)&pxc, g_xc);

    const int4* src4 = (const int4*)ei;
    const int4* dst4 = (const int4*)(ei + e);

    // CSR build (shared by both SAGE layers)
    k_init<<<(n + 255) / 256, 256>>>(n);
    k_hist<<<1024, 256>>>(dst4, e4);
    k_scan1<<<nb, 1024>>>(n);
    k_fill<<<1024, 256>>>(src4, dst4, e4, nb);

    int gb96 = (n + 95) / 96;
    int gb128 = (n + 127) / 128;
    int gb64 = (n + 63) / 64;

    // x0 = x @ lin0_w + lin0_b
    k_gemm<64, 64, 96, 4, true, false><<<gb96, 96>>>(x, lin0_w, lin0_b, px0, 64, 0, n);
    // SAGE 1: zl/zr fused   (launch index 5 -> ncu -s 5 profiles this)
    k_gemm2<64, 64, 96, 4><<<gb96, 96>>>(px0, s1_lw, s1_rw, pzl, pzr, n);
    k_aggr<<<(n + 7) / 8, 256>>>(pzl, pzr, s1_lb, px1, n, nb);
    // SAGE 2
    k_gemm2<64, 64, 96, 4><<<gb96, 96>>>(px1, s2_lw, s2_rw, pzl, pzr, n);
    k_aggr<<<(n + 7) / 8, 256>>>(pzl, pzr, s2_lb, px2, n, nb);
    // embedding heads (3 in 1) -> concat buffer
    k_emb3<<<gb128, 128>>>(px0, px1, px2, emb0_w, emb1_w, emb2_w,
                           emb0_b, emb1_b, emb2_b, pcat, n);
    // merge + fused gate (writes g_xc, g_g, g_gm)
    k_merge<<<gb64, 64>>>(pcat, merge_w, merge_b, gate_w, gate_b, batch, pxc, n);
    // attention pooling + fused final
    k_pool<<<(n + 255) / 256, 256>>>(v_w, v_b, batch, out_w, out_b, out, n);
}